// round 12
// baseline (speedup 1.0000x reference)
#include <cuda_runtime.h>
#include <math.h>

// ---------------- problem constants ----------------
#define NT      256          // threads per block
#define TILE    5120         // envelope outputs per block
#define WIN     240
#define PADW    120
#define CPT     21           // d-elements per thread (NT*CPT=5376 >= TILE+WIN-1=5359)
#define LP      (NT * CPT)   // padded scan length 5376
#define OUT_PT  (TILE / NT)  // 20 outputs per thread
#define EPSF    1e-6f
#define MAXBLK  8192
#define SOFF    3            // smem shift so interior float4 stage is 16B-aligned

// ---------------- scratch (no allocation allowed) ----------------
__device__ double g_s1[MAXBLK];   // per-block sum(diff)
__device__ double g_s2[MAXBLK];   // per-block sum(diff * Et)
__device__ float  g_mx[MAXBLK];   // per-block max(Et)
__device__ int    g_count = 0;    // ticket counter (last block finalizes, then resets)

// Coalesced stage of x[base .. base+LP] into s[SOFF .. SOFF+LP] (0 outside [0,N)).
// Interior tiles use aligned float4 LDG/STS (base+1 = 5120*bx-120 ≡ 0 mod 4).
__device__ __forceinline__ void stage(const float* __restrict__ xr,
                                      int j0, int N, float* __restrict__ s)
{
    const int tid  = threadIdx.x;
    const int base = j0 - PADW - 1;          // x-index of stage element k=0
    if (base >= 0 && base + LP < N) {
        if (tid == 0) s[SOFF] = xr[base];                  // k = 0
        const float4* xv4 = reinterpret_cast<const float4*>(xr + base + 1);
        float4* s4 = reinterpret_cast<float4*>(s + 4);     // s alignas(16), s+4 is 16B-aligned
        for (int v = tid; v < LP / 4; v += NT)             // k = 1+4v .. 4+4v
            s4[v] = xv4[v];
    } else {
        for (int k = tid; k <= LP; k += NT) {
            int t = base + k;
            s[k + SOFF] = ((unsigned)t < (unsigned)N) ? xr[t] : 0.f;
        }
    }
}

// In-place scan over the staged buffer:
//   dp[k] = d[j0+k-PADW], d[t] = (1<=t<N) ? |x[t]-x[t-1]| : 0, 0 for k>=L
// On return, s[k+SOFF] = inclusive prefix sum of dp[0..k].
// Caller must have staged s and issued a __syncthreads() before the first call.
__device__ __forceinline__ void scan_inplace(int j0, int N, int L,
                                             float* __restrict__ s,
                                             float* __restrict__ s_warp)
{
    const int tid  = threadIdx.x;
    const int lane = tid & 31;
    const int wid  = tid >> 5;
    const int c0   = tid * CPT;

    // per-thread chunk: diffs + running prefix in registers
    // (chunk stride 21 coprime with 32 banks -> conflict-free LDS)
    float pref[CPT];
    float xprev = s[c0 + SOFF];
    float run = 0.f;
#pragma unroll
    for (int i = 0; i < CPT; i++) {
        int k = c0 + i;
        float xi = s[k + 1 + SOFF];
        int t = j0 + k - PADW;
        float d = (t >= 1 && t < N && k < L) ? fabsf(xi - xprev) : 0.f;
        run += d;
        pref[i] = run;
        xprev = xi;
    }

    // shuffle scan over the 256 chunk totals
    float tot = run;
#pragma unroll
    for (int off = 1; off < 32; off <<= 1) {
        float v = __shfl_up_sync(0xFFFFFFFFu, tot, off);
        if (lane >= off) tot += v;
    }
    if (lane == 31) s_warp[wid] = tot;
    __syncthreads();                        // stage reads done; s_warp published
    if (wid == 0) {
        float w = (lane < (NT / 32)) ? s_warp[lane] : 0.f;
#pragma unroll
        for (int off = 1; off < (NT / 32); off <<= 1) {
            float v = __shfl_up_sync(0xFFFFFFFFu, w, off);
            if (lane >= off) w += v;
        }
        if (lane < (NT / 32)) s_warp[lane] = w;
    }
    __syncthreads();

    const float add = ((wid > 0) ? s_warp[wid - 1] : 0.f) + (tot - run);
#pragma unroll
    for (int i = 0; i < CPT; i++) s[c0 + i + SOFF] = pref[i] + add;
    __syncthreads();                        // prefix visible; s_warp reusable
}

// One kernel does everything. Per tile: Ep, Et, per-block partials; the last
// block to finish reduces all partials:  loss_row = 0.2*S1 + 0.8*S2/(max+eps)
__global__ __launch_bounds__(NT) void fusedKernel(const float* __restrict__ yp,
                                                  const float* __restrict__ yt,
                                                  float* __restrict__ out,
                                                  int N, int nOut, int tiles, int B,
                                                  double invCount)
{
    __shared__ alignas(16) float s_t[LP + 8];
    __shared__ alignas(16) float s_p[LP + 8];
    __shared__ float  s_warp[NT / 32];
    __shared__ double r1[NT / 32], r2[NT / 32];
    __shared__ float  rm[NT / 32];
    __shared__ int    s_isLast;
    __shared__ double srow[16];

    const int row = blockIdx.y;
    const int j0  = blockIdx.x * TILE;
    const int L   = TILE + WIN - 1;

    // issue ALL global loads up front (both signals in flight together)
    stage(yt + (size_t)row * N, j0, N, s_t);
    stage(yp + (size_t)row * N, j0, N, s_p);
    __syncthreads();

    // scans are pure smem/shuffle work, fully covered by the staged data
    scan_inplace(j0, N, L, s_t, s_warp);
    scan_inplace(j0, N, L, s_p, s_warp);

    const float invW = 1.0f / (float)WIN;
    const int tid  = threadIdx.x;
    const int lane = tid & 31;
    const int wid  = tid >> 5;

    float f1 = 0.f, f2 = 0.f, m = 0.f;
#pragma unroll
    for (int oi = 0; oi < OUT_PT; oi++) {
        int i = tid + oi * NT;             // strided -> conflict-free shared reads
        int j = j0 + i;
        if (j < nOut) {
            float pt = (i > 0) ? s_t[i - 1 + SOFF] : 0.f;
            float pp = (i > 0) ? s_p[i - 1 + SOFF] : 0.f;
            float Et = (s_t[i + WIN - 1 + SOFF] - pt) * invW;
            float Ep = (s_p[i + WIN - 1 + SOFF] - pp) * invW;
            float diff = fabsf(__logf(Ep + EPSF) - __logf(Et + EPSF));  // 2x MUFU.LG2
            f1 += diff;
            f2 += diff * Et;
            m = fmaxf(m, Et);
        }
    }
    double a1 = (double)f1, a2 = (double)f2;
#pragma unroll
    for (int off = 16; off > 0; off >>= 1) {
        a1 += __shfl_down_sync(0xFFFFFFFFu, a1, off);
        a2 += __shfl_down_sync(0xFFFFFFFFu, a2, off);
        m   = fmaxf(m, __shfl_down_sync(0xFFFFFFFFu, m, off));
    }
    if (lane == 0) { r1[wid] = a1; r2[wid] = a2; rm[wid] = m; }
    __syncthreads();
    if (tid < 32) {
        a1 = (lane < (NT / 32)) ? r1[lane] : 0.0;
        a2 = (lane < (NT / 32)) ? r2[lane] : 0.0;
        m  = (lane < (NT / 32)) ? rm[lane] : 0.f;
#pragma unroll
        for (int off = (NT / 64); off > 0; off >>= 1) {
            a1 += __shfl_down_sync(0xFFFFFFFFu, a1, off);
            a2 += __shfl_down_sync(0xFFFFFFFFu, a2, off);
            m   = fmaxf(m, __shfl_down_sync(0xFFFFFFFFu, m, off));
        }
        if (lane == 0) {
            size_t b = (size_t)row * tiles + blockIdx.x;
            g_s1[b] = a1;
            g_s2[b] = a2;
            g_mx[b] = m;
            __threadfence();                       // publish before ticket
            int prev = atomicAdd(&g_count, 1);
            s_isLast = (prev == tiles * B - 1);
        }
    }
    __syncthreads();

    if (s_isLast) {
        // last block: reduce all per-block partials. warp w handles rows w, w+8.
        __threadfence();                           // acquire published partials
        for (int r = wid; r < B; r += (NT / 32)) {
            double s1 = 0.0, s2 = 0.0;
            float  mm = 0.f;
            for (int t = lane; t < tiles; t += 32) {
                size_t b = (size_t)r * tiles + t;
                s1 += g_s1[b];
                s2 += g_s2[b];
                mm  = fmaxf(mm, g_mx[b]);
            }
#pragma unroll
            for (int off = 16; off > 0; off >>= 1) {
                s1 += __shfl_down_sync(0xFFFFFFFFu, s1, off);
                s2 += __shfl_down_sync(0xFFFFFFFFu, s2, off);
                mm  = fmaxf(mm, __shfl_down_sync(0xFFFFFFFFu, mm, off));
            }
            if (lane == 0)
                srow[r] = 0.2 * s1 + 0.8 * s2 / ((double)mm + (double)EPSF);
        }
        __syncthreads();
        if (tid == 0) {
            double tot = 0.0;
            for (int r = 0; r < B; r++) tot += srow[r];
            out[0] = (float)(tot * invCount);
            g_count = 0;                           // reset for next graph replay
        }
    }
}

extern "C" void kernel_launch(void* const* d_in, const int* in_sizes, int n_in,
                              void* d_out, int out_size)
{
    const float* yp = (const float*)d_in[0];
    const float* yt = (const float*)d_in[1];

    const int B = 16;
    const int N = in_sizes[0] / B;       // 480000
    const int nOut = N + 1;              // 480001
    const int tiles = (nOut + TILE - 1) / TILE;   // 94
    dim3 grid(tiles, B);

    const double invCount = 1.0 / ((double)B * (double)nOut);
    fusedKernel<<<grid, NT>>>(yp, yt, (float*)d_out, N, nOut, tiles, B, invCount);
}